// round 1
// baseline (speedup 1.0000x reference)
#include <cuda_runtime.h>

// Problem constants
#define BB   16
#define HH   64
#define WW   64
#define CI   256
#define CO   256
#define NTAP 9          // 3x3
#define KTOT (NTAP*CI)  // 2304

// Scratch (device globals: allocation-free per harness rules)
__device__ float g_K2[CI * CO];     // sum over taps of kernel^2, [ci][co]
__device__ float g_dmod[BB * CO];   // demod factor, [b][co]

// ---------------------------------------------------------------------------
// Prep kernel 1: K2[ci][co] = sum_tap kernel[tap,ci,co]^2
// ---------------------------------------------------------------------------
__global__ void k2_kernel(const float* __restrict__ kern) {
    int ci = blockIdx.x;
    int co = threadIdx.x;
    float s = 0.f;
#pragma unroll
    for (int t = 0; t < NTAP; ++t) {
        float v = kern[(t * CI + ci) * CO + co];
        s += v * v;
    }
    g_K2[ci * CO + co] = s;
}

// ---------------------------------------------------------------------------
// Prep kernel 2: dmod[b][co] = rsqrt( sum_ci (style[b,ci]+1)^2 * K2[ci][co] + 1e-8 )
// ---------------------------------------------------------------------------
__global__ void dmod_kernel(const float* __restrict__ style) {
    __shared__ float sm2[CI];
    int b  = blockIdx.x;
    int co = threadIdx.x;
    float st = style[b * CI + co] + 1.f;
    sm2[co] = st * st;
    __syncthreads();
    float acc = 1e-8f;
#pragma unroll 8
    for (int ci = 0; ci < CI; ++ci)
        acc += sm2[ci] * g_K2[ci * CO + co];
    g_dmod[b * CO + co] = rsqrtf(acc);
}

// ---------------------------------------------------------------------------
// Main: implicit GEMM, M=B*H*W=65536, N=256, K=2304, tf32 mma.sync m16n8k8
// CTA tile 128(M) x 128(N), Ktile=32. 256 threads = 8 warps (2M x 4N).
// ---------------------------------------------------------------------------

__device__ __forceinline__ unsigned f2tf(float f) {
    unsigned u;
    asm("cvt.rna.tf32.f32 %0, %1;" : "=r"(u) : "f"(f));
    return u;
}

__device__ __forceinline__ void mma_tf32(float& d0, float& d1, float& d2, float& d3,
                                         unsigned a0, unsigned a1, unsigned a2, unsigned a3,
                                         unsigned b0, unsigned b1) {
    asm volatile(
        "mma.sync.aligned.m16n8k8.row.col.f32.tf32.tf32.f32 "
        "{%0,%1,%2,%3}, {%4,%5,%6,%7}, {%8,%9}, {%0,%1,%2,%3};\n"
        : "+f"(d0), "+f"(d1), "+f"(d2), "+f"(d3)
        : "r"(a0), "r"(a1), "r"(a2), "r"(a3), "r"(b0), "r"(b1));
}

__global__ __launch_bounds__(256)
void modconv_main(const float* __restrict__ x,
                  const float* __restrict__ style,
                  const float* __restrict__ kern,
                  float* __restrict__ out) {
    // Smem: A pad 32->36 => a-frag bank (4m+k)%32 all-distinct (conflict-free)
    //       B pad 128->136 => b-frag bank (8k+n)%32 all-distinct (conflict-free)
    __shared__ unsigned As[128][36];
    __shared__ unsigned Bs[32][136];
    __shared__ float s_mod[CI];
    __shared__ float s_dmod[128];

    const int tid  = threadIdx.x;
    const int n0   = blockIdx.x * 128;          // output-channel tile base
    const int pos0 = blockIdx.y * 128;          // flat spatial base (2 rows of one image)
    const int b    = pos0 >> 12;                // 4096 positions per image
    const int h0   = (pos0 >> 6) & 63;

    s_mod[tid] = style[b * CI + tid] + 1.f;     // tid in [0,256) == CI
    if (tid < 128) s_dmod[tid] = g_dmod[b * CO + n0 + tid];
    __syncthreads();

    float acc[4][4][4];
#pragma unroll
    for (int mt = 0; mt < 4; ++mt)
#pragma unroll
        for (int nt = 0; nt < 4; ++nt)
#pragma unroll
            for (int i = 0; i < 4; ++i) acc[mt][nt][i] = 0.f;

    const int lane  = tid & 31;
    const int wid   = tid >> 5;
    const int warpM = (wid & 1) * 64;
    const int warpN = (wid >> 1) * 32;

    float4 ax[4];   // stage regs for A (modulated fp32)
    float4 bx[4];   // stage regs for B

    // A load: thread covers 4 rows {mb, mb+32, mb+64, mb+96}, 4 consecutive ci
    const int a_mb = tid >> 3;
    const int a_cg = (tid & 7) * 4;
    // B load: thread covers 4 k-rows {r, r+8, r+16, r+24}, 4 consecutive co
    const int b_r = tid >> 5;
    const int b_c = (tid & 31) * 4;

    auto loadA = [&](int kt) {
        int k0  = kt * 32;
        int tap = k0 >> 8;                       // 32 | 256 => chunk inside one tap
        int ci  = (k0 & 255) + a_cg;
        int dh  = tap / 3 - 1, dw = tap % 3 - 1;
#pragma unroll
        for (int i = 0; i < 4; ++i) {
            int m = a_mb + 32 * i;
            int h = h0 + (m >> 6) + dh;
            int w = (m & 63) + dw;
            if ((unsigned)h < 64u && (unsigned)w < 64u) {
                const float4 v = *(const float4*)&x[(((size_t)(b << 6) + h) * 64 + w) * CI + ci];
                float4 r;
                r.x = v.x * s_mod[ci + 0];
                r.y = v.y * s_mod[ci + 1];
                r.z = v.z * s_mod[ci + 2];
                r.w = v.w * s_mod[ci + 3];
                ax[i] = r;
            } else {
                ax[i] = make_float4(0.f, 0.f, 0.f, 0.f);
            }
        }
    };
    auto loadB = [&](int kt) {
        int k0 = kt * 32;
#pragma unroll
        for (int i = 0; i < 4; ++i)
            bx[i] = *(const float4*)&kern[(size_t)(k0 + b_r + 8 * i) * CO + n0 + b_c];
    };

    loadA(0);
    loadB(0);

    const int KITERS = KTOT / 32;  // 72
    for (int kt = 0; kt < KITERS; ++kt) {
        // store stage -> smem (tf32 convert)
#pragma unroll
        for (int i = 0; i < 4; ++i) {
            uint4 s;
            s.x = f2tf(ax[i].x); s.y = f2tf(ax[i].y);
            s.z = f2tf(ax[i].z); s.w = f2tf(ax[i].w);
            *(uint4*)&As[a_mb + 32 * i][a_cg] = s;
        }
#pragma unroll
        for (int i = 0; i < 4; ++i) {
            uint4 s;
            s.x = f2tf(bx[i].x); s.y = f2tf(bx[i].y);
            s.z = f2tf(bx[i].z); s.w = f2tf(bx[i].w);
            *(uint4*)&Bs[b_r + 8 * i][b_c] = s;
        }
        __syncthreads();

        if (kt + 1 < KITERS) {   // prefetch next tile into regs, overlap with mma
            loadA(kt + 1);
            loadB(kt + 1);
        }

        const int ar = lane >> 2, ac = lane & 3;
#pragma unroll
        for (int ks = 0; ks < 4; ++ks) {
            const int kk = ks * 8;
            unsigned af[4][4];
#pragma unroll
            for (int mt = 0; mt < 4; ++mt) {
                int mb = warpM + mt * 16;
                af[mt][0] = As[mb + ar    ][kk + ac    ];
                af[mt][1] = As[mb + ar + 8][kk + ac    ];
                af[mt][2] = As[mb + ar    ][kk + ac + 4];
                af[mt][3] = As[mb + ar + 8][kk + ac + 4];
            }
            unsigned bf[4][2];
#pragma unroll
            for (int nt = 0; nt < 4; ++nt) {
                int nb = warpN + nt * 8 + ar;
                bf[nt][0] = Bs[kk + ac    ][nb];
                bf[nt][1] = Bs[kk + ac + 4][nb];
            }
#pragma unroll
            for (int mt = 0; mt < 4; ++mt)
#pragma unroll
                for (int nt = 0; nt < 4; ++nt)
                    mma_tf32(acc[mt][nt][0], acc[mt][nt][1], acc[mt][nt][2], acc[mt][nt][3],
                             af[mt][0], af[mt][1], af[mt][2], af[mt][3],
                             bf[nt][0], bf[nt][1]);
        }
        __syncthreads();
    }

    // Epilogue: demodulate per (b, co) and store
#pragma unroll
    for (int mt = 0; mt < 4; ++mt) {
#pragma unroll
        for (int nt = 0; nt < 4; ++nt) {
            int r0 = warpM + mt * 16 + (lane >> 2);
            int c0 = warpN + nt * 8 + (lane & 3) * 2;
            float d0 = s_dmod[c0], d1 = s_dmod[c0 + 1];
            size_t base = (size_t)(pos0 + r0) * CO + n0 + c0;
            float2 o0 = { acc[mt][nt][0] * d0, acc[mt][nt][1] * d1 };
            *(float2*)&out[base] = o0;
            float2 o1 = { acc[mt][nt][2] * d0, acc[mt][nt][3] * d1 };
            *(float2*)&out[base + (size_t)8 * CO] = o1;
        }
    }
}

// ---------------------------------------------------------------------------
extern "C" void kernel_launch(void* const* d_in, const int* in_sizes, int n_in,
                              void* d_out, int out_size) {
    const float* x     = (const float*)d_in[0];
    const float* style = (const float*)d_in[1];
    const float* kern  = (const float*)d_in[2];
    float* out = (float*)d_out;

    k2_kernel<<<CI, CO>>>(kern);
    dmod_kernel<<<BB, CO>>>(style);

    dim3 grid(CO / 128, (BB * HH * WW) / 128);   // (2, 512)
    modconv_main<<<grid, 256>>>(x, style, kern, out);
}